// round 1
// baseline (speedup 1.0000x reference)
#include <cuda_runtime.h>
#include <math.h>

#define SEQ 4096
#define DM  1024
#define NH  16
#define DK  64

// Scratch (allocation-guard-safe __device__ globals): Q,K,V projections + attn out
__device__ float g_Q[SEQ * DM];
__device__ float g_K[SEQ * DM];
__device__ float g_V[SEQ * DM];
__device__ float g_O[SEQ * DM];

// ---------------------------------------------------------------------------
// GEMM: Y[M][N] = X[M][K] @ W[N][K]^T   (K = N = DM = 1024)
// BM=BN=128, BK=16, 256 threads, 8x8 microtile per thread.
// Both operands are K-contiguous -> transpose on smem store, float4 loads.
// ---------------------------------------------------------------------------
__global__ __launch_bounds__(256) void gemm_xwt(
    const float* __restrict__ X, const float* __restrict__ W,
    float* __restrict__ Y)
{
    __shared__ __align__(16) float As[16][132];   // [k][m], padded
    __shared__ __align__(16) float Bs[16][132];   // [k][n], padded

    const int tid = threadIdx.x;
    const int tx  = tid & 15;       // 0..15 -> n direction
    const int ty  = tid >> 4;       // 0..15 -> m direction
    const int bm  = blockIdx.y;
    const int bn  = blockIdx.x;

    const float* Xg = X + (size_t)(bm * 128) * DM;
    const float* Wg = W + (size_t)(bn * 128) * DM;

    float acc[8][8];
#pragma unroll
    for (int i = 0; i < 8; i++)
#pragma unroll
        for (int j = 0; j < 8; j++) acc[i][j] = 0.f;

    for (int kt = 0; kt < DM; kt += 16) {
#pragma unroll
        for (int it = 0; it < 2; it++) {
            int idx = tid + it * 256;        // 0..511
            int row = idx >> 2;              // 0..127
            int c4  = (idx & 3) * 4;         // 0,4,8,12
            float4 va = *reinterpret_cast<const float4*>(Xg + (size_t)row * DM + kt + c4);
            As[c4 + 0][row] = va.x; As[c4 + 1][row] = va.y;
            As[c4 + 2][row] = va.z; As[c4 + 3][row] = va.w;
            float4 vb = *reinterpret_cast<const float4*>(Wg + (size_t)row * DM + kt + c4);
            Bs[c4 + 0][row] = vb.x; Bs[c4 + 1][row] = vb.y;
            Bs[c4 + 2][row] = vb.z; Bs[c4 + 3][row] = vb.w;
        }
        __syncthreads();

#pragma unroll
        for (int k = 0; k < 16; k++) {
            float a[8], b[8];
            *reinterpret_cast<float4*>(a)     = *reinterpret_cast<float4*>(&As[k][ty * 8]);
            *reinterpret_cast<float4*>(a + 4) = *reinterpret_cast<float4*>(&As[k][ty * 8 + 4]);
            *reinterpret_cast<float4*>(b)     = *reinterpret_cast<float4*>(&Bs[k][tx * 8]);
            *reinterpret_cast<float4*>(b + 4) = *reinterpret_cast<float4*>(&Bs[k][tx * 8 + 4]);
#pragma unroll
            for (int i = 0; i < 8; i++)
#pragma unroll
                for (int j = 0; j < 8; j++)
                    acc[i][j] = fmaf(a[i], b[j], acc[i][j]);
        }
        __syncthreads();
    }

#pragma unroll
    for (int i = 0; i < 8; i++) {
        size_t row = (size_t)(bm * 128 + ty * 8 + i);
        float* yp = Y + row * DM + bn * 128 + tx * 8;
        *reinterpret_cast<float4*>(yp)     = make_float4(acc[i][0], acc[i][1], acc[i][2], acc[i][3]);
        *reinterpret_cast<float4*>(yp + 4) = make_float4(acc[i][4], acc[i][5], acc[i][6], acc[i][7]);
    }
}

// ---------------------------------------------------------------------------
// Flash attention, fp32. One CTA = (head h, 64-row Q block).
// Br = Bc = 64, d = 64, 256 threads, 4x4 microtile per thread.
// Online softmax; P tile shares smem with K tile. Scale folded into Q load.
// ---------------------------------------------------------------------------
__global__ __launch_bounds__(256) void flash_attn(
    const float* __restrict__ Q, const float* __restrict__ K,
    const float* __restrict__ V, float* __restrict__ O)
{
    extern __shared__ __align__(16) float sm[];
    float* Qs  = sm;                 // [64][68] transposed: Qs[d][i]
    float* KPs = sm + 64 * 68;       // [64][68] K transposed Ks[d][j]; later P^T: Ps[j][i]
    float* Vs  = sm + 2 * 64 * 68;   // [64][68] Vs[r][c]

    const int tid = threadIdx.x;
    const int tx  = tid & 15;        // column group (j / c)
    const int ty  = tid >> 4;        // row group (i)
    const int h   = blockIdx.x;
    const int qb  = blockIdx.y;
    const float scale = 0.125f;      // 1/sqrt(64)

    // Load Q tile (64 x 64) transposed, scale folded in.
#pragma unroll
    for (int it = 0; it < 4; it++) {
        int idx = tid + it * 256;            // 0..1023
        int r   = idx >> 4;                  // 0..63
        int c4  = (idx & 15) * 4;            // 0..60
        float4 v = *reinterpret_cast<const float4*>(
            Q + (size_t)(qb * 64 + r) * DM + h * DK + c4);
        Qs[(c4 + 0) * 68 + r] = v.x * scale;
        Qs[(c4 + 1) * 68 + r] = v.y * scale;
        Qs[(c4 + 2) * 68 + r] = v.z * scale;
        Qs[(c4 + 3) * 68 + r] = v.w * scale;
    }

    float o[4][4];
    float m[4], l[4];
#pragma unroll
    for (int a = 0; a < 4; a++) {
        m[a] = -1e30f; l[a] = 0.f;
#pragma unroll
        for (int c = 0; c < 4; c++) o[a][c] = 0.f;
    }

    for (int kv = 0; kv < SEQ / 64; kv++) {
        __syncthreads();   // previous iteration done reading KPs/Vs (and Qs load on iter 0)

        // Load K tile transposed + V tile straight.
#pragma unroll
        for (int it = 0; it < 4; it++) {
            int idx = tid + it * 256;
            int r   = idx >> 4;
            int c4  = (idx & 15) * 4;
            float4 kvv = *reinterpret_cast<const float4*>(
                K + (size_t)(kv * 64 + r) * DM + h * DK + c4);
            KPs[(c4 + 0) * 68 + r] = kvv.x;
            KPs[(c4 + 1) * 68 + r] = kvv.y;
            KPs[(c4 + 2) * 68 + r] = kvv.z;
            KPs[(c4 + 3) * 68 + r] = kvv.w;
            float4 vv = *reinterpret_cast<const float4*>(
                V + (size_t)(kv * 64 + r) * DM + h * DK + c4);
            *reinterpret_cast<float4*>(&Vs[r * 68 + c4]) = vv;
        }
        __syncthreads();

        // S = (Q*scale) @ K^T  -- 4x4 fragment
        float s[4][4];
#pragma unroll
        for (int a = 0; a < 4; a++)
#pragma unroll
            for (int b = 0; b < 4; b++) s[a][b] = 0.f;

#pragma unroll 16
        for (int d = 0; d < 64; d++) {
            float qa[4], kb[4];
            *reinterpret_cast<float4*>(qa) = *reinterpret_cast<float4*>(&Qs[d * 68 + ty * 4]);
            *reinterpret_cast<float4*>(kb) = *reinterpret_cast<float4*>(&KPs[d * 68 + tx * 4]);
#pragma unroll
            for (int a = 0; a < 4; a++)
#pragma unroll
                for (int b = 0; b < 4; b++)
                    s[a][b] = fmaf(qa[a], kb[b], s[a][b]);
        }

        // Online softmax per row (allreduce across the 16 tx lanes, same warp half)
#pragma unroll
        for (int a = 0; a < 4; a++) {
            float mx = fmaxf(fmaxf(s[a][0], s[a][1]), fmaxf(s[a][2], s[a][3]));
#pragma unroll
            for (int off = 1; off < 16; off <<= 1)
                mx = fmaxf(mx, __shfl_xor_sync(0xffffffffu, mx, off));
            float mn   = fmaxf(m[a], mx);
            float corr = __expf(m[a] - mn);
            float rs   = 0.f;
#pragma unroll
            for (int b = 0; b < 4; b++) {
                s[a][b] = __expf(s[a][b] - mn);
                rs += s[a][b];
            }
#pragma unroll
            for (int off = 1; off < 16; off <<= 1)
                rs += __shfl_xor_sync(0xffffffffu, rs, off);
            l[a] = l[a] * corr + rs;
            m[a] = mn;
#pragma unroll
            for (int c = 0; c < 4; c++) o[a][c] *= corr;
        }

        __syncthreads();   // everyone done reading K from KPs

        // Write P transposed into KPs: Ps[j][i] = P[i][j]
#pragma unroll
        for (int a = 0; a < 4; a++)
#pragma unroll
            for (int b = 0; b < 4; b++)
                KPs[(tx * 4 + b) * 68 + ty * 4 + a] = s[a][b];

        __syncthreads();

        // O += P @ V
#pragma unroll 16
        for (int r = 0; r < 64; r++) {
            float pa[4], va[4];
            *reinterpret_cast<float4*>(pa) = *reinterpret_cast<float4*>(&KPs[r * 68 + ty * 4]);
            *reinterpret_cast<float4*>(va) = *reinterpret_cast<float4*>(&Vs[r * 68 + tx * 4]);
#pragma unroll
            for (int a = 0; a < 4; a++)
#pragma unroll
                for (int c = 0; c < 4; c++)
                    o[a][c] = fmaf(pa[a], va[c], o[a][c]);
        }
    }

    // Normalize and store
#pragma unroll
    for (int a = 0; a < 4; a++) {
        float inv = 1.f / l[a];
        float4 ov = make_float4(o[a][0] * inv, o[a][1] * inv, o[a][2] * inv, o[a][3] * inv);
        *reinterpret_cast<float4*>(
            O + (size_t)(qb * 64 + ty * 4 + a) * DM + h * DK + tx * 4) = ov;
    }
}

// ---------------------------------------------------------------------------
extern "C" void kernel_launch(void* const* d_in, const int* in_sizes, int n_in,
                              void* d_out, int out_size)
{
    const float* query = (const float*)d_in[0];
    const float* key_t = (const float*)d_in[1];
    const float* value = (const float*)d_in[2];
    const float* w_q   = (const float*)d_in[3];
    const float* w_k   = (const float*)d_in[4];
    const float* w_v   = (const float*)d_in[5];
    const float* w_o   = (const float*)d_in[6];
    float* out = (float*)d_out;

    float *Qp, *Kp, *Vp, *Op;
    cudaGetSymbolAddress((void**)&Qp, g_Q);
    cudaGetSymbolAddress((void**)&Kp, g_K);
    cudaGetSymbolAddress((void**)&Vp, g_V);
    cudaGetSymbolAddress((void**)&Op, g_O);

    const int smem_attn = 3 * 64 * 68 * (int)sizeof(float);   // 52224 B
    cudaFuncSetAttribute(flash_attn, cudaFuncAttributeMaxDynamicSharedMemorySize, smem_attn);

    dim3 ggrid(DM / 128, SEQ / 128);   // (8, 32)
    gemm_xwt<<<ggrid, 256>>>(query, w_q, Qp);
    gemm_xwt<<<ggrid, 256>>>(key_t, w_k, Kp);
    gemm_xwt<<<ggrid, 256>>>(value, w_v, Vp);

    dim3 agrid(NH, SEQ / 64);          // (16, 64)
    flash_attn<<<agrid, 256, smem_attn>>>(Qp, Kp, Vp, Op);

    gemm_xwt<<<ggrid, 256>>>(Op, w_o, out);
}

// round 2
// speedup vs baseline: 1.0002x; 1.0002x over previous
#include <cuda_runtime.h>
#include <math.h>

#define SEQ 4096
#define DM  1024
#define NH  16
#define DK  64

// Scratch (allocation-guard-safe __device__ globals): Q,K,V projections + attn out
__device__ float g_Q[SEQ * DM];
__device__ float g_K[SEQ * DM];
__device__ float g_V[SEQ * DM];
__device__ float g_O[SEQ * DM];

// ---------------------------------------------------------------------------
// GEMM: Y[M][N] = X[M][K] @ W[N][K]^T   (K = N = DM = 1024)
// BM=BN=128, BK=16, 256 threads, 8x8 microtile per thread.
// Both operands are K-contiguous -> transpose on smem store, float4 loads.
// ---------------------------------------------------------------------------
__global__ __launch_bounds__(256) void gemm_xwt(
    const float* __restrict__ X, const float* __restrict__ W,
    float* __restrict__ Y)
{
    __shared__ __align__(16) float As[16][132];   // [k][m], padded
    __shared__ __align__(16) float Bs[16][132];   // [k][n], padded

    const int tid = threadIdx.x;
    const int tx  = tid & 15;       // 0..15 -> n direction
    const int ty  = tid >> 4;       // 0..15 -> m direction
    const int bm  = blockIdx.y;
    const int bn  = blockIdx.x;

    const float* Xg = X + (size_t)(bm * 128) * DM;
    const float* Wg = W + (size_t)(bn * 128) * DM;

    float acc[8][8];
#pragma unroll
    for (int i = 0; i < 8; i++)
#pragma unroll
        for (int j = 0; j < 8; j++) acc[i][j] = 0.f;

    for (int kt = 0; kt < DM; kt += 16) {
#pragma unroll
        for (int it = 0; it < 2; it++) {
            int idx = tid + it * 256;        // 0..511
            int row = idx >> 2;              // 0..127
            int c4  = (idx & 3) * 4;         // 0,4,8,12
            float4 va = *reinterpret_cast<const float4*>(Xg + (size_t)row * DM + kt + c4);
            As[c4 + 0][row] = va.x; As[c4 + 1][row] = va.y;
            As[c4 + 2][row] = va.z; As[c4 + 3][row] = va.w;
            float4 vb = *reinterpret_cast<const float4*>(Wg + (size_t)row * DM + kt + c4);
            Bs[c4 + 0][row] = vb.x; Bs[c4 + 1][row] = vb.y;
            Bs[c4 + 2][row] = vb.z; Bs[c4 + 3][row] = vb.w;
        }
        __syncthreads();

#pragma unroll
        for (int k = 0; k < 16; k++) {
            float a[8], b[8];
            *reinterpret_cast<float4*>(a)     = *reinterpret_cast<float4*>(&As[k][ty * 8]);
            *reinterpret_cast<float4*>(a + 4) = *reinterpret_cast<float4*>(&As[k][ty * 8 + 4]);
            *reinterpret_cast<float4*>(b)     = *reinterpret_cast<float4*>(&Bs[k][tx * 8]);
            *reinterpret_cast<float4*>(b + 4) = *reinterpret_cast<float4*>(&Bs[k][tx * 8 + 4]);
#pragma unroll
            for (int i = 0; i < 8; i++)
#pragma unroll
                for (int j = 0; j < 8; j++)
                    acc[i][j] = fmaf(a[i], b[j], acc[i][j]);
        }
        __syncthreads();
    }

#pragma unroll
    for (int i = 0; i < 8; i++) {
        size_t row = (size_t)(bm * 128 + ty * 8 + i);
        float* yp = Y + row * DM + bn * 128 + tx * 8;
        *reinterpret_cast<float4*>(yp)     = make_float4(acc[i][0], acc[i][1], acc[i][2], acc[i][3]);
        *reinterpret_cast<float4*>(yp + 4) = make_float4(acc[i][4], acc[i][5], acc[i][6], acc[i][7]);
    }
}

// ---------------------------------------------------------------------------
// Flash attention, fp32. One CTA = (head h, 64-row Q block).
// Br = Bc = 64, d = 64, 256 threads, 4x4 microtile per thread.
// Online softmax; P tile shares smem with K tile. Scale folded into Q load.
// ---------------------------------------------------------------------------
__global__ __launch_bounds__(256) void flash_attn(
    const float* __restrict__ Q, const float* __restrict__ K,
    const float* __restrict__ V, float* __restrict__ O)
{
    extern __shared__ __align__(16) float sm[];
    float* Qs  = sm;                 // [64][68] transposed: Qs[d][i]
    float* KPs = sm + 64 * 68;       // [64][68] K transposed Ks[d][j]; later P^T: Ps[j][i]
    float* Vs  = sm + 2 * 64 * 68;   // [64][68] Vs[r][c]

    const int tid = threadIdx.x;
    const int tx  = tid & 15;        // column group (j / c)
    const int ty  = tid >> 4;        // row group (i)
    const int h   = blockIdx.x;
    const int qb  = blockIdx.y;
    const float scale = 0.125f;      // 1/sqrt(64)

    // Load Q tile (64 x 64) transposed, scale folded in.
#pragma unroll
    for (int it = 0; it < 4; it++) {
        int idx = tid + it * 256;            // 0..1023
        int r   = idx >> 4;                  // 0..63
        int c4  = (idx & 15) * 4;            // 0..60
        float4 v = *reinterpret_cast<const float4*>(
            Q + (size_t)(qb * 64 + r) * DM + h * DK + c4);
        Qs[(c4 + 0) * 68 + r] = v.x * scale;
        Qs[(c4 + 1) * 68 + r] = v.y * scale;
        Qs[(c4 + 2) * 68 + r] = v.z * scale;
        Qs[(c4 + 3) * 68 + r] = v.w * scale;
    }

    float o[4][4];
    float m[4], l[4];
#pragma unroll
    for (int a = 0; a < 4; a++) {
        m[a] = -1e30f; l[a] = 0.f;
#pragma unroll
        for (int c = 0; c < 4; c++) o[a][c] = 0.f;
    }

    for (int kv = 0; kv < SEQ / 64; kv++) {
        __syncthreads();   // previous iteration done reading KPs/Vs (and Qs load on iter 0)

        // Load K tile transposed + V tile straight.
#pragma unroll
        for (int it = 0; it < 4; it++) {
            int idx = tid + it * 256;
            int r   = idx >> 4;
            int c4  = (idx & 15) * 4;
            float4 kvv = *reinterpret_cast<const float4*>(
                K + (size_t)(kv * 64 + r) * DM + h * DK + c4);
            KPs[(c4 + 0) * 68 + r] = kvv.x;
            KPs[(c4 + 1) * 68 + r] = kvv.y;
            KPs[(c4 + 2) * 68 + r] = kvv.z;
            KPs[(c4 + 3) * 68 + r] = kvv.w;
            float4 vv = *reinterpret_cast<const float4*>(
                V + (size_t)(kv * 64 + r) * DM + h * DK + c4);
            *reinterpret_cast<float4*>(&Vs[r * 68 + c4]) = vv;
        }
        __syncthreads();

        // S = (Q*scale) @ K^T  -- 4x4 fragment
        float s[4][4];
#pragma unroll
        for (int a = 0; a < 4; a++)
#pragma unroll
            for (int b = 0; b < 4; b++) s[a][b] = 0.f;

#pragma unroll 16
        for (int d = 0; d < 64; d++) {
            float qa[4], kb[4];
            *reinterpret_cast<float4*>(qa) = *reinterpret_cast<float4*>(&Qs[d * 68 + ty * 4]);
            *reinterpret_cast<float4*>(kb) = *reinterpret_cast<float4*>(&KPs[d * 68 + tx * 4]);
#pragma unroll
            for (int a = 0; a < 4; a++)
#pragma unroll
                for (int b = 0; b < 4; b++)
                    s[a][b] = fmaf(qa[a], kb[b], s[a][b]);
        }

        // Online softmax per row (allreduce across the 16 tx lanes, same warp half)
#pragma unroll
        for (int a = 0; a < 4; a++) {
            float mx = fmaxf(fmaxf(s[a][0], s[a][1]), fmaxf(s[a][2], s[a][3]));
#pragma unroll
            for (int off = 1; off < 16; off <<= 1)
                mx = fmaxf(mx, __shfl_xor_sync(0xffffffffu, mx, off));
            float mn   = fmaxf(m[a], mx);
            float corr = __expf(m[a] - mn);
            float rs   = 0.f;
#pragma unroll
            for (int b = 0; b < 4; b++) {
                s[a][b] = __expf(s[a][b] - mn);
                rs += s[a][b];
            }
#pragma unroll
            for (int off = 1; off < 16; off <<= 1)
                rs += __shfl_xor_sync(0xffffffffu, rs, off);
            l[a] = l[a] * corr + rs;
            m[a] = mn;
#pragma unroll
            for (int c = 0; c < 4; c++) o[a][c] *= corr;
        }

        __syncthreads();   // everyone done reading K from KPs

        // Write P transposed into KPs: Ps[j][i] = P[i][j]
#pragma unroll
        for (int a = 0; a < 4; a++)
#pragma unroll
            for (int b = 0; b < 4; b++)
                KPs[(tx * 4 + b) * 68 + ty * 4 + a] = s[a][b];

        __syncthreads();

        // O += P @ V
#pragma unroll 16
        for (int r = 0; r < 64; r++) {
            float pa[4], va[4];
            *reinterpret_cast<float4*>(pa) = *reinterpret_cast<float4*>(&KPs[r * 68 + ty * 4]);
            *reinterpret_cast<float4*>(va) = *reinterpret_cast<float4*>(&Vs[r * 68 + tx * 4]);
#pragma unroll
            for (int a = 0; a < 4; a++)
#pragma unroll
                for (int c = 0; c < 4; c++)
                    o[a][c] = fmaf(pa[a], va[c], o[a][c]);
        }
    }

    // Normalize and store
#pragma unroll
    for (int a = 0; a < 4; a++) {
        float inv = 1.f / l[a];
        float4 ov = make_float4(o[a][0] * inv, o[a][1] * inv, o[a][2] * inv, o[a][3] * inv);
        *reinterpret_cast<float4*>(
            O + (size_t)(qb * 64 + ty * 4 + a) * DM + h * DK + tx * 4) = ov;
    }
}

// ---------------------------------------------------------------------------
extern "C" void kernel_launch(void* const* d_in, const int* in_sizes, int n_in,
                              void* d_out, int out_size)
{
    const float* query = (const float*)d_in[0];
    const float* key_t = (const float*)d_in[1];
    const float* value = (const float*)d_in[2];
    const float* w_q   = (const float*)d_in[3];
    const float* w_k   = (const float*)d_in[4];
    const float* w_v   = (const float*)d_in[5];
    const float* w_o   = (const float*)d_in[6];
    float* out = (float*)d_out;

    float *Qp, *Kp, *Vp, *Op;
    cudaGetSymbolAddress((void**)&Qp, g_Q);
    cudaGetSymbolAddress((void**)&Kp, g_K);
    cudaGetSymbolAddress((void**)&Vp, g_V);
    cudaGetSymbolAddress((void**)&Op, g_O);

    const int smem_attn = 3 * 64 * 68 * (int)sizeof(float);   // 52224 B
    cudaFuncSetAttribute(flash_attn, cudaFuncAttributeMaxDynamicSharedMemorySize, smem_attn);

    dim3 ggrid(DM / 128, SEQ / 128);   // (8, 32)
    gemm_xwt<<<ggrid, 256>>>(query, w_q, Qp);
    gemm_xwt<<<ggrid, 256>>>(key_t, w_k, Kp);
    gemm_xwt<<<ggrid, 256>>>(value, w_v, Vp);

    dim3 agrid(NH, SEQ / 64);          // (16, 64)
    flash_attn<<<agrid, 256, smem_attn>>>(Qp, Kp, Vp, Op);

    gemm_xwt<<<ggrid, 256>>>(Op, w_o, out);
}